// round 13
// baseline (speedup 1.0000x reference)
#include <cuda_runtime.h>
#include <cuda_fp16.h>
#include <cstdint>

// TopKNoisyRouter: fused dual GEMM [N,1024]x[1024,128], fp16 2-way split
// (3 HMMA products, fp32 accum, W pre-scaled by 32). BM=64 / occ-3 variant
// of the r12 kernel: CTA tile 64x128 (warp tile 32x32, acc 32 regs),
// A 2-buf (16KB) + B 3-buf ring (48KB) = 64KB smem -> 3 CTAs/SM (24 warps).
// Same pipeline: convert(c)->A[b]; wait_group 1 -> __syncthreads ->
// issue B(c+2) -> staggered/interleaved MMA. cp.async addressing hoisted to
// one base + constant offsets. Fused noisy-top-2 + softmax epilogue.

#define DK 1024
#define NE 64
#define BM 64
#define KC 32
#define NCHUNK (DK / KC)      // 32
#define PLANE_A 4096          // 64 rows x 32 fp16 (64B rows, 2 rows/128B)
#define PLANE_B 8192          // 128 rows x 32 fp16
#define OFF_B (4 * PLANE_A)   // 16384: A 2 bufs x 2 planes; then B 3 bufs x 2
#define SMEM_BYTES 65536      // 16K A + 48K B; epilogue needs 50.2K (fits)

__device__ __half g_w[2][128 * DK];   // fp16(32w), fp16(32w - hi); K-major

__device__ __forceinline__ uint32_t smem_u32(const void* p) {
    uint32_t a;
    asm("{ .reg .u64 t; cvta.to.shared.u64 t, %1; cvt.u32.u64 %0, t; }" : "=r"(a) : "l"(p));
    return a;
}
__device__ __forceinline__ uint32_t swz32(uint32_t r, uint32_t c) {
    return (r >> 1) * 128 + (r & 1) * 64 + (c ^ (((r >> 1) & 3) << 4));
}
__device__ __forceinline__ void cp16(uint32_t dst, const void* src) {
    asm volatile("cp.async.cg.shared.global [%0], [%1], 16;" :: "r"(dst), "l"(src));
}
__device__ __forceinline__ void ldsm4(uint32_t& r0, uint32_t& r1, uint32_t& r2,
                                      uint32_t& r3, uint32_t addr) {
    asm volatile("ldmatrix.sync.aligned.m8n8.x4.shared.b16 {%0,%1,%2,%3}, [%4];"
                 : "=r"(r0), "=r"(r1), "=r"(r2), "=r"(r3) : "r"(addr));
}
__device__ __forceinline__ void mma16816(float* c, const uint32_t* a,
                                         uint32_t b0, uint32_t b1) {
    asm volatile("mma.sync.aligned.m16n8k16.row.col.f32.f16.f16.f32 "
                 "{%0,%1,%2,%3}, {%4,%5,%6,%7}, {%8,%9}, {%0,%1,%2,%3};"
                 : "+f"(c[0]), "+f"(c[1]), "+f"(c[2]), "+f"(c[3])
                 : "r"(a[0]), "r"(a[1]), "r"(a[2]), "r"(a[3]), "r"(b0), "r"(b1));
}
__device__ __forceinline__ float softplusf(float v) {
    return fmaxf(v, 0.0f) + log1pf(expf(-fabsf(v)));
}
__device__ __forceinline__ uint32_t h2u(__half2 h) {
    union { __half2 h; uint32_t u; } v; v.h = h; return v.u;
}

__global__ void prep_weights(const float* __restrict__ wr, const float* __restrict__ wn) {
    int i = blockIdx.x * blockDim.x + threadIdx.x;    // 0 .. 128*1024-1
    int e = i >> 10, k = i & 1023;
    float v = 32.0f * ((e < NE) ? wr[e * DK + k] : wn[(e - NE) * DK + k]);
    __half h = __float2half_rn(v);
    g_w[0][i] = h;
    g_w[1][i] = __float2half_rn(v - __half2float(h));
}

__global__ __launch_bounds__(256, 3)
void router_gemm(const float* __restrict__ x, const float* __restrict__ eps,
                 float* __restrict__ out, float* __restrict__ idx_out, int write_idx)
{
    extern __shared__ char smem[];
    const uint32_t sb = smem_u32(smem);
    const int tid = threadIdx.x;
    const int lane = tid & 31, wid = tid >> 5;
    const int wm = wid & 1, wq = wid >> 1;        // warp tile 32x32 at (wm*32, wq*32)
    const int row0 = blockIdx.x * BM;

    // coalesced zero-fill of this block's output tile [64 x 64]
    {
        float4 z = make_float4(0.f, 0.f, 0.f, 0.f);
        float4* ot = (float4*)(out + (size_t)row0 * NE);
        #pragma unroll
        for (int i = 0; i < 4; ++i) ot[tid + 256 * i] = z;
    }

    // ldmatrix per-lane address pieces
    const int rA = wm * 32 + (lane & 15);
    const uint32_t rowA = (uint32_t)((rA >> 1) * 128 + (rA & 1) * 64);
    const uint32_t xorA = (uint32_t)(((rA >> 1) & 3) << 4);
    const uint32_t cbA  = (uint32_t)((lane >> 4) * 16);
    const int rB = wq * 32 + (lane & 7) + ((lane >> 4) << 3);
    const uint32_t rowB = (uint32_t)((rB >> 1) * 128 + (rB & 1) * 64);
    const uint32_t xorB = (uint32_t)(((rB >> 1) & 3) << 4);
    const uint32_t cbB  = (uint32_t)(((lane >> 3) & 1) * 16);
    const int ksw = wid & 1;     // k-step stagger parity

    // x staging: thread covers row r_x, 8 floats at float-offset q_x*8
    const int r_x = tid >> 2;
    const int q_x = tid & 3;
    const float* xbase = x + (size_t)(row0 + r_x) * DK + q_x * 8;
    const uint32_t rowX = (uint32_t)((r_x >> 1) * 128 + (r_x & 1) * 64);
    const uint32_t xorX = (uint32_t)(((r_x >> 1) & 3) << 4);
    const uint32_t swX  = rowX + (((uint32_t)(q_x * 16)) ^ xorX);

    // hoisted cp.async base (4 copies/chunk at constant offsets)
    const int n0 = tid >> 2, cu0 = (tid & 3) * 16;
    const uint32_t bd0 = sb + OFF_B + swz32((uint32_t)n0, (uint32_t)cu0);
    const __half* bs0 = &g_w[0][n0 * DK + (cu0 >> 1)];

    float acc[2][4][4];
    #pragma unroll
    for (int mt = 0; mt < 2; ++mt)
        #pragma unroll
        for (int nt = 0; nt < 4; ++nt)
            #pragma unroll
            for (int q = 0; q < 4; ++q) acc[mt][nt][q] = 0.f;

    // ---- prologue: x chunk0 -> regs; B chunks 0,1 -> cp.async (2 groups) ----
    float4 xr0 = *(const float4*)(xbase);
    float4 xr1 = *(const float4*)(xbase + 4);
    cp16(bd0,                      bs0);
    cp16(bd0 + 4096,               bs0 + 64 * DK);
    cp16(bd0 + PLANE_B,            bs0 + 128 * DK);
    cp16(bd0 + PLANE_B + 4096,     bs0 + 192 * DK);
    asm volatile("cp.async.commit_group;" ::: "memory");
    {
        const uint32_t bb = 2 * PLANE_B;          // buffer 1
        cp16(bd0 + bb,                  bs0 + KC);
        cp16(bd0 + bb + 4096,           bs0 + KC + 64 * DK);
        cp16(bd0 + bb + PLANE_B,        bs0 + KC + 128 * DK);
        cp16(bd0 + bb + PLANE_B + 4096, bs0 + KC + 192 * DK);
    }
    asm volatile("cp.async.commit_group;" ::: "memory");

    int br = 0;   // B read buffer (c % 3)
    int bp = 2;   // B prefetch buffer ((c+2) % 3)

    #pragma unroll 1
    for (int c = 0; c < NCHUNK; ++c) {
        const int b = c & 1;
        const int kn = ((c + 1) & (NCHUNK - 1)) * KC;   // next x chunk (wraps, safe)
        char* Ab = smem + (uint32_t)(b * 2) * PLANE_A;

        // ---- convert x regs (chunk c) -> A[b]; prefetch next x into regs ----
        {
            float4 f0 = xr0, f1 = xr1;
            xr0 = *(const float4*)(xbase + kn);
            xr1 = *(const float4*)(xbase + kn + 4);
            __half2 a0 = __floats2half2_rn(f0.x, f0.y);
            __half2 a1 = __floats2half2_rn(f0.z, f0.w);
            __half2 a2 = __floats2half2_rn(f1.x, f1.y);
            __half2 a3 = __floats2half2_rn(f1.z, f1.w);
            float2 g0 = __half22float2(a0), g1 = __half22float2(a1);
            float2 g2 = __half22float2(a2), g3 = __half22float2(a3);
            *(uint4*)(Ab + swX) = make_uint4(h2u(a0), h2u(a1), h2u(a2), h2u(a3));
            *(uint4*)(Ab + PLANE_A + swX) = make_uint4(
                h2u(__floats2half2_rn(f0.x - g0.x, f0.y - g0.y)),
                h2u(__floats2half2_rn(f0.z - g1.x, f0.w - g1.y)),
                h2u(__floats2half2_rn(f1.x - g2.x, f1.y - g2.y)),
                h2u(__floats2half2_rn(f1.z - g3.x, f1.w - g3.y)));
        }

        // B group for chunk c complete for THIS thread, then publish.
        asm volatile("cp.async.wait_group 1;" ::: "memory");
        __syncthreads();                         // A[b] + B[br] visible

        // ---- issue B chunk c+2 into buffer bp; commit ALWAYS (empty on
        //      tail) to keep group accounting exact ----
        if (c + 2 < NCHUNK) {
            const __half* bsk = bs0 + (c + 2) * KC;
            const uint32_t bb = (uint32_t)(bp * 2) * PLANE_B;
            cp16(bd0 + bb,                  bsk);
            cp16(bd0 + bb + 4096,           bsk + 64 * DK);
            cp16(bd0 + bb + PLANE_B,        bsk + 128 * DK);
            cp16(bd0 + bb + PLANE_B + 4096, bsk + 192 * DK);
        }
        asm volatile("cp.async.commit_group;" ::: "memory");

        // ---- MMA: 3 split products over 2 k16 steps, warp-parity stagger,
        //      ldsm groups interleaved with MMA groups ----
        const uint32_t Ah = sb + (uint32_t)(b * 2) * PLANE_A;
        const uint32_t Al = Ah + PLANE_A;
        const uint32_t Bh = sb + OFF_B + (uint32_t)(br * 2) * PLANE_B;
        const uint32_t Bl = Bh + PLANE_B;
        #pragma unroll
        for (int t = 0; t < 2; ++t) {
            const int ks = t ^ ksw;              // even warps 0,1; odd 1,0
            const uint32_t kb = (uint32_t)(ks * 32);
            const uint32_t ca = (kb + cbA) ^ xorA;
            const uint32_t cc = (kb + cbB) ^ xorB;
            uint32_t a[2][4], bh[8], bl[8];
            // group 1: A-hi + B-hi, then hh product
            #pragma unroll
            for (int mt = 0; mt < 2; ++mt)
                ldsm4(a[mt][0], a[mt][1], a[mt][2], a[mt][3], Ah + rowA + mt * 1024 + ca);
            ldsm4(bh[0], bh[1], bh[2], bh[3], Bh + rowB + cc);
            ldsm4(bh[4], bh[5], bh[6], bh[7], Bh + rowB + 1024 + cc);
            #pragma unroll
            for (int mt = 0; mt < 2; ++mt)
                #pragma unroll
                for (int nt = 0; nt < 4; ++nt)
                    mma16816(acc[mt][nt], a[mt], bh[2 * nt], bh[2 * nt + 1]);
            // group 2: B-lo, then hl product
            ldsm4(bl[0], bl[1], bl[2], bl[3], Bl + rowB + cc);
            ldsm4(bl[4], bl[5], bl[6], bl[7], Bl + rowB + 1024 + cc);
            #pragma unroll
            for (int mt = 0; mt < 2; ++mt)
                #pragma unroll
                for (int nt = 0; nt < 4; ++nt)
                    mma16816(acc[mt][nt], a[mt], bl[2 * nt], bl[2 * nt + 1]);
            // group 3: A-lo, then lh product
            #pragma unroll
            for (int mt = 0; mt < 2; ++mt)
                ldsm4(a[mt][0], a[mt][1], a[mt][2], a[mt][3], Al + rowA + mt * 1024 + ca);
            #pragma unroll
            for (int mt = 0; mt < 2; ++mt)
                #pragma unroll
                for (int nt = 0; nt < 4; ++nt)
                    mma16816(acc[mt][nt], a[mt], bh[2 * nt], bh[2 * nt + 1]);
        }

        br = (br == 2) ? 0 : br + 1;
        bp = (bp == 2) ? 0 : bp + 1;
    }
    __syncthreads();

    // ---- stage C (scaled 1/32) + eps to smem, fused top-2 epilogue ----
    float* Cs = (float*)smem;                    // [64][130] = 33280 B
    float* Es = (float*)(smem + 33280);          // [64][66]  = 16896 B
    {
        const float INV32 = 0.03125f;
        const int crow = wm * 32 + (lane >> 2);
        const int ccol = wq * 32 + (lane & 3) * 2;
        #pragma unroll
        for (int mt = 0; mt < 2; ++mt)
            #pragma unroll
            for (int nt = 0; nt < 4; ++nt) {
                float* p0 = Cs + (crow + mt * 16) * 130 + ccol + nt * 8;
                p0[0] = acc[mt][nt][0] * INV32; p0[1] = acc[mt][nt][1] * INV32;
                float* p1 = p0 + 8 * 130;
                p1[0] = acc[mt][nt][2] * INV32; p1[1] = acc[mt][nt][3] * INV32;
            }
        const float4* eg = (const float4*)(eps + (size_t)row0 * NE);
        #pragma unroll
        for (int i4 = 0; i4 < 4; ++i4) {
            int u = tid + 256 * i4;                 // 0..1023
            float4 v = eg[u];
            int r = u >> 4, e = (u & 15) * 4;
            float* d = Es + r * 66 + e;
            d[0] = v.x; d[1] = v.y; d[2] = v.z; d[3] = v.w;
        }
    }
    __syncthreads();

    if (tid < BM) {
        const int r = tid;
        const size_t n = (size_t)row0 + r;
        const float* lg = Cs + r * 130;
        const float* er = Es + r * 66;
        const float NEG = __int_as_float(0xff800000);
        float m1 = NEG, m2 = NEG; int i1 = 0, i2 = 0;
        #pragma unroll
        for (int e = 0; e < NE; ++e) {
            float v = lg[e] + er[e] * softplusf(lg[e + 64]);
            if (v > m1) { m2 = m1; i2 = i1; m1 = v; i1 = e; }
            else if (v > m2) { m2 = v; i2 = e; }
        }
        float ee = expf(m2 - m1);
        float inv = 1.0f / (1.0f + ee);
        out[n * NE + i1] = inv;
        out[n * NE + i2] = ee * inv;
        if (write_idx) {
            idx_out[n * 2 + 0] = (float)i1;
            idx_out[n * 2 + 1] = (float)i2;
        }
    }
}

extern "C" void kernel_launch(void* const* d_in, const int* in_sizes, int n_in,
                              void* d_out, int out_size)
{
    const float* x   = (const float*)d_in[0];
    const float* wr  = (const float*)d_in[1];
    const float* wn  = (const float*)d_in[2];
    const float* eps = (const float*)d_in[3];
    float* out = (float*)d_out;

    const int N = in_sizes[3] / NE;
    const int write_idx = (out_size >= N * NE + N * 2) ? 1 : 0;
    float* idx_out = out + (size_t)N * NE;

    prep_weights<<<(128 * DK) / 256, 256>>>(wr, wn);

    cudaFuncSetAttribute(router_gemm,
                         cudaFuncAttributeMaxDynamicSharedMemorySize, SMEM_BYTES);
    router_gemm<<<N / BM, 256, SMEM_BYTES>>>(x, eps, out, idx_out, write_idx);
}